// round 13
// baseline (speedup 1.0000x reference)
#include <cuda_runtime.h>
#include <cuda_fp16.h>
#include <math.h>
#include <stdint.h>

#define B_ROWS 16384
#define D_DIM  2048
#define H_DIM  512
#define NPART  8          // 512 / 64 n-chunks
#define NCHUNKS 4         // batch chunks for pipelining
#define CHUNK_ROWS (B_ROWS / NCHUNKS)        // 4096
#define LO_SCALE   2048.0f          // 2^11
#define LO_INV     4.8828125e-4f    // 2^-11

// ------------------------- device scratch -------------------------
__device__ __half g_xs[2ull * B_ROWS * D_DIM];   // x split hi / scaled-lo
__device__ __half g_ws[2ull * H_DIM * D_DIM];    // W1^T split hi / scaled-lo [H,D]
__device__ float  g_partial[B_ROWS * NPART];
__device__ float  g_l1row[B_ROWS];

// ------------------------- helpers --------------------------------
__device__ __forceinline__ uint32_t smem_u32(const void* p) {
    uint32_t a;
    asm("{ .reg .u64 t; cvta.to.shared.u64 t, %1; cvt.u32.u64 %0, t; }" : "=r"(a) : "l"(p));
    return a;
}
__device__ __forceinline__ uint32_t swz128(uint32_t b) { return b ^ ((b >> 3) & 0x70u); }

__device__ __forceinline__ void cp16(uint32_t dst, const void* src) {
    asm volatile("cp.async.cg.shared.global [%0], [%1], 16;" :: "r"(dst), "l"(src) : "memory");
}
__device__ __forceinline__ void cp_commit() {
    asm volatile("cp.async.commit_group;" ::: "memory");
}
template <int N>
__device__ __forceinline__ void cp_wait() {
    asm volatile("cp.async.wait_group %0;" :: "n"(N) : "memory");
}
__device__ __forceinline__ void ldsm4(uint32_t* r, uint32_t addr) {
    asm volatile("ldmatrix.sync.aligned.m8n8.x4.shared.b16 {%0,%1,%2,%3}, [%4];"
                 : "=r"(r[0]), "=r"(r[1]), "=r"(r[2]), "=r"(r[3]) : "r"(addr));
}
__device__ __forceinline__ void mma16816(float* c, const uint32_t* a,
                                         uint32_t b0, uint32_t b1) {
    asm volatile(
        "mma.sync.aligned.m16n8k16.row.col.f32.f16.f16.f32 "
        "{%0,%1,%2,%3}, {%4,%5,%6,%7}, {%8,%9}, {%0,%1,%2,%3};"
        : "+f"(c[0]), "+f"(c[1]), "+f"(c[2]), "+f"(c[3])
        : "r"(a[0]), "r"(a[1]), "r"(a[2]), "r"(a[3]), "r"(b0), "r"(b1));
}

__device__ __forceinline__ void split2s(float f, __half& h, __half& l) {
    h = __float2half_rn(f);
    l = __float2half_rn((f - __half2float(h)) * LO_SCALE);   // scaled: stays normal
}

// --------------- stage 0a: split x chunk into hi / scaled-lo -------
__global__ void __launch_bounds__(256) convert_x(const float* __restrict__ x,
                                                 int row_base)
{
    size_t base = (size_t)row_base * D_DIM;
    size_t i4 = base + ((size_t)blockIdx.x * 256 + threadIdx.x) * 4;
    float4 v = *reinterpret_cast<const float4*>(x + i4);
    __half h[4], l[4];
    split2s(v.x, h[0], l[0]);
    split2s(v.y, h[1], l[1]);
    split2s(v.z, h[2], l[2]);
    split2s(v.w, h[3], l[3]);
    const size_t P = (size_t)B_ROWS * D_DIM;
    *reinterpret_cast<uint2*>(&g_xs[i4])     = *reinterpret_cast<uint2*>(h);
    *reinterpret_cast<uint2*>(&g_xs[P + i4]) = *reinterpret_cast<uint2*>(l);
}

// --------------- stage 0b: split + transpose W1 --------------------
__global__ void __launch_bounds__(256) convert_w1(const float* __restrict__ W1)
{
    size_t idx = (size_t)blockIdx.x * 256 + threadIdx.x;   // over [D, H]
    if (idx >= (size_t)D_DIM * H_DIM) return;
    int k = (int)(idx / H_DIM);
    int n = (int)(idx % H_DIM);
    __half h, l;
    split2s(W1[idx], h, l);
    const size_t P = (size_t)H_DIM * D_DIM;
    size_t o = (size_t)n * D_DIM + k;
    g_ws[o]     = h;
    g_ws[P + o] = l;
}

// --------------- stage 1: HMMA split-2 GEMM + fused epilogue -------
// CTA tile: 128(M) x 64(N), BK=32, 3-stage cp.async, 2 CTAs/SM.
// Row layout: [32 fp16 hi | 32 fp16 lo] = 128B, SW128 swizzle.
// Per stage: A 16KB + B 8KB = 24KB; 3 stages = 72KB.
#define STAGE_BYTES 24576
#define SM_DYN (3 * STAGE_BYTES + 1024)

__global__ void __launch_bounds__(256, 2) gemm_predictor(
    const float* __restrict__ b1, const float* __restrict__ W2, int mtile_base)
{
    extern __shared__ char smem_raw[];
    __shared__ float red[128][4];

    const uint32_t sb  = (smem_u32(smem_raw) + 1023u) & ~1023u;
    const int tid  = threadIdx.x;
    const int lane = tid & 31;
    const int w    = tid >> 5;
    const int wm   = w >> 2;          // 0..1  (M64 rows)
    const int wn   = w & 3;           // 0..3  (N16 cols)
    const int m0   = (mtile_base + blockIdx.y) * 128;
    const int n0   = blockIdx.x * 64;
    const size_t PX = (size_t)B_ROWS * D_DIM;
    const size_t PW = (size_t)H_DIM * D_DIM;

    float chi[4][2][4];   // hh
    float clo[4][2][4];   // hl + lh (scaled by 2^11)
#pragma unroll
    for (int i = 0; i < 4; i++)
#pragma unroll
        for (int j = 0; j < 2; j++)
#pragma unroll
            for (int e = 0; e < 4; e++) { chi[i][j][e] = 0.f; clo[i][j][e] = 0.f; }

    // stage layout: A @ +0 (16KB: row = [hi32|lo32]), B @ +16384 (8KB)
    auto load_tiles = [&](int stage, int kt) {
        const int k0 = kt * 32;
        const uint32_t abase = sb + (uint32_t)stage * STAGE_BYTES;
        const uint32_t bbase = abase + 16384u;
        // A: 128 rows x 8 chunks(16B) -> 1024 cp16, 4 per thread
#pragma unroll
        for (int i = 0; i < 4; ++i) {
            int u = tid + i * 256;
            int row = u >> 3, q = u & 7;
            int p = q >> 2, cc = q & 3;        // plane, 16B-chunk in plane
            const __half* src = g_xs + (size_t)p * PX +
                                (size_t)(m0 + row) * D_DIM + k0 + cc * 8;
            cp16(abase + swz128((uint32_t)(row * 128 + q * 16)), src);
        }
        // B: 64 rows x 8 chunks -> 512 cp16, 2 per thread
#pragma unroll
        for (int i = 0; i < 2; ++i) {
            int u = tid + i * 256;
            int row = u >> 3, q = u & 7;
            int p = q >> 2, cc = q & 3;
            const __half* src = g_ws + (size_t)p * PW +
                                (size_t)(n0 + row) * D_DIM + k0 + cc * 8;
            cp16(bbase + swz128((uint32_t)(row * 128 + q * 16)), src);
        }
    };

    auto compute = [&](int stage) {
        const uint32_t A = sb + (uint32_t)stage * STAGE_BYTES;
        const uint32_t B = A + 16384u;
#pragma unroll
        for (int s = 0; s < 2; ++s) {          // two k16 chunks in BK=32
            const int chi_b = (s * 2 + (lane >> 4)) * 16;   // hi bytes 0..63
            uint32_t brh[4], brl[4];
            {
                int row = wn * 16 + (lane & 15);
                uint32_t base = (uint32_t)(row * 128);
                ldsm4(brh, B + swz128(base + chi_b));
                ldsm4(brl, B + swz128(base + 64 + chi_b));  // lo bytes 64..127
            }
#pragma unroll
            for (int mt = 0; mt < 4; ++mt) {
                int row = wm * 64 + mt * 16 + (lane & 15);
                uint32_t base = (uint32_t)(row * 128);
                uint32_t ah[4], al[4];
                ldsm4(ah, A + swz128(base + chi_b));
                ldsm4(al, A + swz128(base + 64 + chi_b));
#pragma unroll
                for (int nt = 0; nt < 2; ++nt) {
                    const uint32_t bh0 = brh[nt], bh1 = brh[nt + 2];
                    const uint32_t bl0 = brl[nt], bl1 = brl[nt + 2];
                    mma16816(chi[mt][nt], ah, bh0, bh1);   // hh
                    mma16816(clo[mt][nt], ah, bl0, bl1);   // hl (x2^11)
                    mma16816(clo[mt][nt], al, bh0, bh1);   // lh (x2^11)
                }
            }
        }
    };

    const int NK = 64;                          // 2048 / 32
    load_tiles(0, 0); cp_commit();
    load_tiles(1, 1); cp_commit();
    int st = 0;
    for (int kt = 0; kt < NK; ++kt) {
        if (kt + 2 < NK) {
            load_tiles((st + 2) % 3, kt + 2);
            cp_commit();
            cp_wait<2>();
        } else if (kt + 1 < NK) {
            cp_wait<1>();
        } else {
            cp_wait<0>();
        }
        __syncthreads();
        compute(st);
        st = (st + 1) % 3;
        __syncthreads();
    }

    // epilogue: relu((chi + clo*2^-11) + b1) dot W2 over 64 cols -> partial
#pragma unroll
    for (int mt = 0; mt < 4; ++mt) {
#pragma unroll
        for (int h = 0; h < 2; ++h) {
            float p = 0.f;
#pragma unroll
            for (int nt = 0; nt < 2; ++nt)
#pragma unroll
                for (int e = 0; e < 2; ++e) {
                    int col = n0 + wn * 16 + nt * 8 + (lane & 3) * 2 + e;
                    float v = fmaf(clo[mt][nt][h * 2 + e], LO_INV,
                                   chi[mt][nt][h * 2 + e]) + b1[col];
                    v = fmaxf(v, 0.f);
                    p = fmaf(v, W2[col], p);
                }
            p += __shfl_xor_sync(0xffffffffu, p, 1);
            p += __shfl_xor_sync(0xffffffffu, p, 2);
            if ((lane & 3) == 0) {
                int row = wm * 64 + mt * 16 + (lane >> 2) + 8 * h;
                red[row][wn] = p;
            }
        }
    }
    __syncthreads();
    if (tid < 128) {
        float s = red[tid][0] + red[tid][1] + red[tid][2] + red[tid][3];
        g_partial[(size_t)(m0 + tid) * NPART + blockIdx.x] = s;
    }
}

// ------- stage 2: fused sparsity + exact radix select --------------
__global__ void __launch_bounds__(256) select_mask_kernel(
    const float* __restrict__ x, const float* __restrict__ b2,
    float* __restrict__ out_sp,
    float* __restrict__ out_sparse, float* __restrict__ out_mask,
    float* __restrict__ out_act, int row_base)
{
    __shared__ unsigned int hist[256];
    __shared__ unsigned int wsum[8];
    __shared__ float        wl1[8];
    __shared__ unsigned int wcnt[8];
    __shared__ unsigned int s_prefix, s_kk;

    const int row  = row_base + blockIdx.x;
    const int tid  = threadIdx.x;
    const int lane = tid & 31;
    const int wid  = tid >> 5;
    const float* xr = x + (size_t)row * D_DIM;

    float4 v0 = *reinterpret_cast<const float4*>(&xr[tid * 4]);
    float4 v1 = *reinterpret_cast<const float4*>(&xr[1024 + tid * 4]);
    unsigned int key[8];
    key[0] = __float_as_uint(fabsf(v0.x));
    key[1] = __float_as_uint(fabsf(v0.y));
    key[2] = __float_as_uint(fabsf(v0.z));
    key[3] = __float_as_uint(fabsf(v0.w));
    key[4] = __float_as_uint(fabsf(v1.x));
    key[5] = __float_as_uint(fabsf(v1.y));
    key[6] = __float_as_uint(fabsf(v1.z));
    key[7] = __float_as_uint(fabsf(v1.w));

    if (tid == 0) {
        float s = b2[0];
#pragma unroll
        for (int cc = 0; cc < NPART; cc++) s += g_partial[(size_t)row * NPART + cc];
        float sig = 1.f / (1.f + expf(-s));
        float sp  = 0.05f + 0.25f * sig;
        out_sp[row] = sp;
        int k = (int)rintf((float)D_DIM * (1.f - sp));   // round half-even
        s_prefix = 0u;
        s_kk = (unsigned int)((k < 1) ? 1 : k);
    }
    hist[tid] = 0u;
    __syncthreads();

#pragma unroll
    for (int shift = 24; shift >= 0; shift -= 8) {
        const unsigned int prefix = s_prefix;
        const unsigned int kcur   = s_kk;
        const unsigned int himask = (shift == 24) ? 0u : (0xFFFFFFFFu << (shift + 8));
#pragma unroll
        for (int i = 0; i < 8; i++) {
            if ((key[i] & himask) == prefix)
                atomicAdd(&hist[(key[i] >> shift) & 255u], 1u);
        }
        __syncthreads();
        const unsigned int own = hist[tid];
        unsigned int v = own;
#pragma unroll
        for (int off = 1; off < 32; off <<= 1) {
            unsigned int t = __shfl_up_sync(0xffffffffu, v, off);
            if (lane >= off) v += t;
        }
        if (lane == 31) wsum[wid] = v;
        __syncthreads();
        if (tid < 8) {
            unsigned int ws = wsum[tid];
#pragma unroll
            for (int off = 1; off < 8; off <<= 1) {
                unsigned int t = __shfl_up_sync(0xffu, ws, off, 8);
                if (tid >= off) ws += t;
            }
            wsum[tid] = ws;
        }
        __syncthreads();
        const unsigned int cum  = v + (wid ? wsum[wid - 1] : 0u);
        const unsigned int prev = cum - own;
        if (cum >= kcur && prev < kcur) {
            s_prefix = prefix | ((unsigned int)tid << shift);
            s_kk     = kcur - prev;
        }
        hist[tid] = 0u;
        __syncthreads();
    }

    const unsigned int thr = s_prefix;

    unsigned int cnt = 0;
    float l1 = 0.f;
    float vv[8] = {v0.x, v0.y, v0.z, v0.w, v1.x, v1.y, v1.z, v1.w};
    float mk[8], sx[8];
#pragma unroll
    for (int i = 0; i < 8; i++) {
        bool m = key[i] > thr;
        mk[i] = m ? 1.f : 0.f;
        sx[i] = m ? vv[i] : 0.f;
        if (m) { cnt++; l1 += __uint_as_float(key[i]); }
    }
    *reinterpret_cast<float4*>(&out_mask  [(size_t)row * D_DIM + tid * 4])        = *reinterpret_cast<float4*>(&mk[0]);
    *reinterpret_cast<float4*>(&out_mask  [(size_t)row * D_DIM + 1024 + tid * 4]) = *reinterpret_cast<float4*>(&mk[4]);
    *reinterpret_cast<float4*>(&out_sparse[(size_t)row * D_DIM + tid * 4])        = *reinterpret_cast<float4*>(&sx[0]);
    *reinterpret_cast<float4*>(&out_sparse[(size_t)row * D_DIM + 1024 + tid * 4]) = *reinterpret_cast<float4*>(&sx[4]);

#pragma unroll
    for (int off = 16; off > 0; off >>= 1) {
        cnt += __shfl_xor_sync(0xffffffffu, cnt, off);
        l1  += __shfl_xor_sync(0xffffffffu, l1, off);
    }
    if (lane == 0) { wcnt[wid] = cnt; wl1[wid] = l1; }
    __syncthreads();
    if (tid == 0) {
        unsigned int c = 0; float s = 0.f;
#pragma unroll
        for (int wz = 0; wz < 8; wz++) { c += wcnt[wz]; s += wl1[wz]; }
        out_act[row] = (float)c / (float)D_DIM;
        g_l1row[row] = s;
    }
}

// ---------------- stage 3: deterministic l1 mean -------------------
__global__ void __launch_bounds__(1024) l1_reduce(float* __restrict__ out_l1)
{
    __shared__ float sm[1024];
    const int tid = threadIdx.x;
    float s = 0.f;
    for (int i = tid; i < B_ROWS; i += 1024) s += g_l1row[i];
    sm[tid] = s;
    __syncthreads();
    for (int off = 512; off > 0; off >>= 1) {
        if (tid < off) sm[tid] += sm[tid + off];
        __syncthreads();
    }
    if (tid == 0) out_l1[0] = sm[0] / (float)B_ROWS;
}

// ------------- streams/events (pre-main static init) ---------------
static cudaStream_t g_sG, g_sS;
static cudaEvent_t  g_evX[NCHUNKS];
static cudaEvent_t  g_evG[NCHUNKS];
static cudaEvent_t  g_evS;
static const bool g_res_init = [](){
    cudaStreamCreateWithFlags(&g_sG, cudaStreamNonBlocking);
    cudaStreamCreateWithFlags(&g_sS, cudaStreamNonBlocking);
    for (int i = 0; i < NCHUNKS; i++) {
        cudaEventCreateWithFlags(&g_evX[i], cudaEventDisableTiming);
        cudaEventCreateWithFlags(&g_evG[i], cudaEventDisableTiming);
    }
    cudaEventCreateWithFlags(&g_evS, cudaEventDisableTiming);
    return true;
}();

// ---------------- launch: 3-lane chunk pipeline --------------------
extern "C" void kernel_launch(void* const* d_in, const int* in_sizes, int n_in,
                              void* d_out, int out_size)
{
    const float* x  = (const float*)d_in[0];
    const float* W1 = (const float*)d_in[1];
    const float* b1 = (const float*)d_in[2];
    const float* W2 = (const float*)d_in[3];
    const float* b2 = (const float*)d_in[4];

    float* out        = (float*)d_out;
    float* out_sparse = out;                                   // [B, D]
    float* out_mask   = out + (size_t)B_ROWS * D_DIM;          // [B, D]
    float* out_sp     = out + 2 * (size_t)B_ROWS * D_DIM;      // [B, 1]
    float* out_act    = out_sp + B_ROWS;                       // [B]
    float* out_l1     = out_act + B_ROWS;                      // [1]

    cudaFuncSetAttribute(gemm_predictor,
                         cudaFuncAttributeMaxDynamicSharedMemorySize, SM_DYN);

    cudaStream_t s0 = 0;
    const int conv_grid = (CHUNK_ROWS * D_DIM) / (4 * 256);    // 8192

    convert_w1<<<((size_t)D_DIM * H_DIM) / 256, 256, 0, s0>>>(W1);
    for (int c = 0; c < NCHUNKS; c++) {
        convert_x<<<conv_grid, 256, 0, s0>>>(x, c * CHUNK_ROWS);
        cudaEventRecord(g_evX[c], s0);
    }

    for (int c = 0; c < NCHUNKS; c++) {
        cudaStreamWaitEvent(g_sG, g_evX[c], 0);
        gemm_predictor<<<dim3(8, CHUNK_ROWS / 128), 256, SM_DYN, g_sG>>>(
            b1, W2, c * (CHUNK_ROWS / 128));
        cudaEventRecord(g_evG[c], g_sG);
    }

    for (int c = 0; c < NCHUNKS; c++) {
        cudaStreamWaitEvent(g_sS, g_evG[c], 0);
        select_mask_kernel<<<CHUNK_ROWS, 256, 0, g_sS>>>(
            x, b2, out_sp, out_sparse, out_mask, out_act, c * CHUNK_ROWS);
    }
    cudaEventRecord(g_evS, g_sS);

    cudaStreamWaitEvent(s0, g_evS, 0);
    l1_reduce<<<1, 1024, 0, s0>>>(out_l1);
}

// round 14
// speedup vs baseline: 1.0415x; 1.0415x over previous
#include <cuda_runtime.h>
#include <cuda_fp16.h>
#include <math.h>
#include <stdint.h>

#define B_ROWS 16384
#define D_DIM  2048
#define H_DIM  512
#define NPART  8          // 512 / 64 n-chunks
#define NCHUNKS 8         // batch chunks for pipelining
#define CHUNK_ROWS (B_ROWS / NCHUNKS)        // 2048
#define LO_SCALE   2048.0f          // 2^11
#define LO_INV     4.8828125e-4f    // 2^-11

// ------------------------- device scratch -------------------------
__device__ __half g_xs[2ull * B_ROWS * D_DIM];   // x split hi / scaled-lo
__device__ __half g_ws[2ull * H_DIM * D_DIM];    // W1^T split hi / scaled-lo [H,D]
__device__ float  g_partial[B_ROWS * NPART];
__device__ float  g_l1row[B_ROWS];

// ------------------------- helpers --------------------------------
__device__ __forceinline__ uint32_t smem_u32(const void* p) {
    uint32_t a;
    asm("{ .reg .u64 t; cvta.to.shared.u64 t, %1; cvt.u32.u64 %0, t; }" : "=r"(a) : "l"(p));
    return a;
}
__device__ __forceinline__ uint32_t swz128(uint32_t b) { return b ^ ((b >> 3) & 0x70u); }

__device__ __forceinline__ void cp16(uint32_t dst, const void* src) {
    asm volatile("cp.async.cg.shared.global [%0], [%1], 16;" :: "r"(dst), "l"(src) : "memory");
}
__device__ __forceinline__ void cp_commit() {
    asm volatile("cp.async.commit_group;" ::: "memory");
}
template <int N>
__device__ __forceinline__ void cp_wait() {
    asm volatile("cp.async.wait_group %0;" :: "n"(N) : "memory");
}
__device__ __forceinline__ void ldsm4(uint32_t* r, uint32_t addr) {
    asm volatile("ldmatrix.sync.aligned.m8n8.x4.shared.b16 {%0,%1,%2,%3}, [%4];"
                 : "=r"(r[0]), "=r"(r[1]), "=r"(r[2]), "=r"(r[3]) : "r"(addr));
}
__device__ __forceinline__ void mma16816(float* c, const uint32_t* a,
                                         uint32_t b0, uint32_t b1) {
    asm volatile(
        "mma.sync.aligned.m16n8k16.row.col.f32.f16.f16.f32 "
        "{%0,%1,%2,%3}, {%4,%5,%6,%7}, {%8,%9}, {%0,%1,%2,%3};"
        : "+f"(c[0]), "+f"(c[1]), "+f"(c[2]), "+f"(c[3])
        : "r"(a[0]), "r"(a[1]), "r"(a[2]), "r"(a[3]), "r"(b0), "r"(b1));
}

__device__ __forceinline__ void split2s(float f, __half& h, __half& l) {
    h = __float2half_rn(f);
    l = __float2half_rn((f - __half2float(h)) * LO_SCALE);   // scaled: stays normal
}

// --------------- stage 0a: split x chunk into hi / scaled-lo -------
__global__ void __launch_bounds__(256) convert_x(const float* __restrict__ x,
                                                 int row_base)
{
    size_t base = (size_t)row_base * D_DIM;
    size_t i4 = base + ((size_t)blockIdx.x * 256 + threadIdx.x) * 4;
    float4 v = *reinterpret_cast<const float4*>(x + i4);
    __half h[4], l[4];
    split2s(v.x, h[0], l[0]);
    split2s(v.y, h[1], l[1]);
    split2s(v.z, h[2], l[2]);
    split2s(v.w, h[3], l[3]);
    const size_t P = (size_t)B_ROWS * D_DIM;
    *reinterpret_cast<uint2*>(&g_xs[i4])     = *reinterpret_cast<uint2*>(h);
    *reinterpret_cast<uint2*>(&g_xs[P + i4]) = *reinterpret_cast<uint2*>(l);
}

// --------------- stage 0b: split + transpose W1 --------------------
__global__ void __launch_bounds__(256) convert_w1(const float* __restrict__ W1)
{
    size_t idx = (size_t)blockIdx.x * 256 + threadIdx.x;   // over [D, H]
    if (idx >= (size_t)D_DIM * H_DIM) return;
    int k = (int)(idx / H_DIM);
    int n = (int)(idx % H_DIM);
    __half h, l;
    split2s(W1[idx], h, l);
    const size_t P = (size_t)H_DIM * D_DIM;
    size_t o = (size_t)n * D_DIM + k;
    g_ws[o]     = h;
    g_ws[P + o] = l;
}

// --------------- stage 1: HMMA split-2 GEMM + fused epilogue -------
// CTA tile: 128(M) x 64(N), BK=64. Per chunk grid (8, 16) = 128 CTAs.
#define SM_DYN (98304 + 1024)

__global__ void __launch_bounds__(256, 1) gemm_predictor(
    const float* __restrict__ b1, const float* __restrict__ W2, int mtile_base)
{
    extern __shared__ char smem_raw[];
    __shared__ float red[128][4];

    const uint32_t sb  = (smem_u32(smem_raw) + 1023u) & ~1023u;
    const uint32_t sbB = sb + 65536u;
    const int tid  = threadIdx.x;
    const int lane = tid & 31;
    const int w    = tid >> 5;
    const int wm   = w >> 2;          // 0..1  (M64 rows)
    const int wn   = w & 3;           // 0..3  (N16 cols)
    const int m0   = (mtile_base + blockIdx.y) * 128;
    const int n0   = blockIdx.x * 64;
    const size_t PX = (size_t)B_ROWS * D_DIM;
    const size_t PW = (size_t)H_DIM * D_DIM;

    float chi[4][2][4];   // hh
    float clo[4][2][4];   // hl + lh (scaled by 2^11)
#pragma unroll
    for (int i = 0; i < 4; i++)
#pragma unroll
        for (int j = 0; j < 2; j++)
#pragma unroll
            for (int e = 0; e < 4; e++) { chi[i][j][e] = 0.f; clo[i][j][e] = 0.f; }

    auto load_tiles = [&](int stage, int kt) {
        const int k0 = kt * 64;
#pragma unroll
        for (int p = 0; p < 2; ++p) {
            const __half* asrc = g_xs + (size_t)p * PX;
            const __half* bsrc = g_ws + (size_t)p * PW;
            const uint32_t abase = sb  + (uint32_t)(stage * 2 + p) * 16384u;
            const uint32_t bbase = sbB + (uint32_t)(stage * 2 + p) * 8192u;
#pragma unroll
            for (int i = 0; i < 4; ++i) {          // A: 128 rows
                int u = tid + i * 256;
                int row = u >> 3, cc = u & 7;
                uint32_t soff = swz128((uint32_t)(row * 128 + cc * 16));
                cp16(abase + soff, asrc + (size_t)(m0 + row) * D_DIM + k0 + cc * 8);
            }
#pragma unroll
            for (int i = 0; i < 2; ++i) {          // B: 64 rows
                int u = tid + i * 256;
                int row = u >> 3, cc = u & 7;
                uint32_t soff = swz128((uint32_t)(row * 128 + cc * 16));
                cp16(bbase + soff, bsrc + (size_t)(n0 + row) * D_DIM + k0 + cc * 8);
            }
        }
    };

    auto compute = [&](int stage) {
        const uint32_t A0 = sb  + (uint32_t)(stage * 2 + 0) * 16384u;
        const uint32_t A1 = sb  + (uint32_t)(stage * 2 + 1) * 16384u;
        const uint32_t B0 = sbB + (uint32_t)(stage * 2 + 0) * 8192u;
        const uint32_t B1 = sbB + (uint32_t)(stage * 2 + 1) * 8192u;
#pragma unroll
        for (int s = 0; s < 4; ++s) {
            const int chunk = (s * 2 + (lane >> 4)) * 16;
            uint32_t brh[4], brl[4];
            {
                int row = wn * 16 + (lane & 15);
                uint32_t off = swz128((uint32_t)(row * 128 + chunk));
                ldsm4(brh, B0 + off);
                ldsm4(brl, B1 + off);
            }
#pragma unroll
            for (int mt = 0; mt < 4; ++mt) {
                int row = wm * 64 + mt * 16 + (lane & 15);
                uint32_t off = swz128((uint32_t)(row * 128 + chunk));
                uint32_t ah[4], al[4];
                ldsm4(ah, A0 + off);
                ldsm4(al, A1 + off);
#pragma unroll
                for (int nt = 0; nt < 2; ++nt) {
                    const uint32_t bh0 = brh[nt], bh1 = brh[nt + 2];
                    const uint32_t bl0 = brl[nt], bl1 = brl[nt + 2];
                    mma16816(chi[mt][nt], ah, bh0, bh1);   // hh
                    mma16816(clo[mt][nt], ah, bl0, bl1);   // hl (x2^11)
                    mma16816(clo[mt][nt], al, bh0, bh1);   // lh (x2^11)
                }
            }
        }
    };

    load_tiles(0, 0);
    cp_commit();
    for (int kt = 0; kt < 32; ++kt) {
        if (kt + 1 < 32) {
            load_tiles((kt + 1) & 1, kt + 1);
            cp_commit();
            cp_wait<1>();
        } else {
            cp_wait<0>();
        }
        __syncthreads();
        compute(kt & 1);
        __syncthreads();
    }

    // epilogue: relu((chi + clo*2^-11) + b1) dot W2 over 64 cols -> partial
#pragma unroll
    for (int mt = 0; mt < 4; ++mt) {
#pragma unroll
        for (int h = 0; h < 2; ++h) {
            float p = 0.f;
#pragma unroll
            for (int nt = 0; nt < 2; ++nt)
#pragma unroll
                for (int e = 0; e < 2; ++e) {
                    int col = n0 + wn * 16 + nt * 8 + (lane & 3) * 2 + e;
                    float v = fmaf(clo[mt][nt][h * 2 + e], LO_INV,
                                   chi[mt][nt][h * 2 + e]) + b1[col];
                    v = fmaxf(v, 0.f);
                    p = fmaf(v, W2[col], p);
                }
            p += __shfl_xor_sync(0xffffffffu, p, 1);
            p += __shfl_xor_sync(0xffffffffu, p, 2);
            if ((lane & 3) == 0) {
                int row = wm * 64 + mt * 16 + (lane >> 2) + 8 * h;
                red[row][wn] = p;
            }
        }
    }
    __syncthreads();
    if (tid < 128) {
        float s = red[tid][0] + red[tid][1] + red[tid][2] + red[tid][3];
        g_partial[(size_t)(m0 + tid) * NPART + blockIdx.x] = s;
    }
}

// ------- stage 2: fused sparsity + exact radix select --------------
__global__ void __launch_bounds__(256) select_mask_kernel(
    const float* __restrict__ x, const float* __restrict__ b2,
    float* __restrict__ out_sp,
    float* __restrict__ out_sparse, float* __restrict__ out_mask,
    float* __restrict__ out_act, int row_base)
{
    __shared__ unsigned int hist[256];
    __shared__ unsigned int wsum[8];
    __shared__ float        wl1[8];
    __shared__ unsigned int wcnt[8];
    __shared__ unsigned int s_prefix, s_kk;

    const int row  = row_base + blockIdx.x;
    const int tid  = threadIdx.x;
    const int lane = tid & 31;
    const int wid  = tid >> 5;
    const float* xr = x + (size_t)row * D_DIM;

    float4 v0 = *reinterpret_cast<const float4*>(&xr[tid * 4]);
    float4 v1 = *reinterpret_cast<const float4*>(&xr[1024 + tid * 4]);
    unsigned int key[8];
    key[0] = __float_as_uint(fabsf(v0.x));
    key[1] = __float_as_uint(fabsf(v0.y));
    key[2] = __float_as_uint(fabsf(v0.z));
    key[3] = __float_as_uint(fabsf(v0.w));
    key[4] = __float_as_uint(fabsf(v1.x));
    key[5] = __float_as_uint(fabsf(v1.y));
    key[6] = __float_as_uint(fabsf(v1.z));
    key[7] = __float_as_uint(fabsf(v1.w));

    if (tid == 0) {
        float s = b2[0];
#pragma unroll
        for (int cc = 0; cc < NPART; cc++) s += g_partial[(size_t)row * NPART + cc];
        float sig = 1.f / (1.f + expf(-s));
        float sp  = 0.05f + 0.25f * sig;
        out_sp[row] = sp;
        int k = (int)rintf((float)D_DIM * (1.f - sp));   // round half-even
        s_prefix = 0u;
        s_kk = (unsigned int)((k < 1) ? 1 : k);
    }
    hist[tid] = 0u;
    __syncthreads();

#pragma unroll
    for (int shift = 24; shift >= 0; shift -= 8) {
        const unsigned int prefix = s_prefix;
        const unsigned int kcur   = s_kk;
        const unsigned int himask = (shift == 24) ? 0u : (0xFFFFFFFFu << (shift + 8));
#pragma unroll
        for (int i = 0; i < 8; i++) {
            if ((key[i] & himask) == prefix)
                atomicAdd(&hist[(key[i] >> shift) & 255u], 1u);
        }
        __syncthreads();
        const unsigned int own = hist[tid];
        unsigned int v = own;
#pragma unroll
        for (int off = 1; off < 32; off <<= 1) {
            unsigned int t = __shfl_up_sync(0xffffffffu, v, off);
            if (lane >= off) v += t;
        }
        if (lane == 31) wsum[wid] = v;
        __syncthreads();
        if (tid < 8) {
            unsigned int ws = wsum[tid];
#pragma unroll
            for (int off = 1; off < 8; off <<= 1) {
                unsigned int t = __shfl_up_sync(0xffu, ws, off, 8);
                if (tid >= off) ws += t;
            }
            wsum[tid] = ws;
        }
        __syncthreads();
        const unsigned int cum  = v + (wid ? wsum[wid - 1] : 0u);
        const unsigned int prev = cum - own;
        if (cum >= kcur && prev < kcur) {
            s_prefix = prefix | ((unsigned int)tid << shift);
            s_kk     = kcur - prev;
        }
        hist[tid] = 0u;
        __syncthreads();
    }

    const unsigned int thr = s_prefix;

    unsigned int cnt = 0;
    float l1 = 0.f;
    float vv[8] = {v0.x, v0.y, v0.z, v0.w, v1.x, v1.y, v1.z, v1.w};
    float mk[8], sx[8];
#pragma unroll
    for (int i = 0; i < 8; i++) {
        bool m = key[i] > thr;
        mk[i] = m ? 1.f : 0.f;
        sx[i] = m ? vv[i] : 0.f;
        if (m) { cnt++; l1 += __uint_as_float(key[i]); }
    }
    *reinterpret_cast<float4*>(&out_mask  [(size_t)row * D_DIM + tid * 4])        = *reinterpret_cast<float4*>(&mk[0]);
    *reinterpret_cast<float4*>(&out_mask  [(size_t)row * D_DIM + 1024 + tid * 4]) = *reinterpret_cast<float4*>(&mk[4]);
    *reinterpret_cast<float4*>(&out_sparse[(size_t)row * D_DIM + tid * 4])        = *reinterpret_cast<float4*>(&sx[0]);
    *reinterpret_cast<float4*>(&out_sparse[(size_t)row * D_DIM + 1024 + tid * 4]) = *reinterpret_cast<float4*>(&sx[4]);

#pragma unroll
    for (int off = 16; off > 0; off >>= 1) {
        cnt += __shfl_xor_sync(0xffffffffu, cnt, off);
        l1  += __shfl_xor_sync(0xffffffffu, l1, off);
    }
    if (lane == 0) { wcnt[wid] = cnt; wl1[wid] = l1; }
    __syncthreads();
    if (tid == 0) {
        unsigned int c = 0; float s = 0.f;
#pragma unroll
        for (int wz = 0; wz < 8; wz++) { c += wcnt[wz]; s += wl1[wz]; }
        out_act[row] = (float)c / (float)D_DIM;
        g_l1row[row] = s;
    }
}

// ---------------- stage 3: deterministic l1 mean -------------------
__global__ void __launch_bounds__(1024) l1_reduce(float* __restrict__ out_l1)
{
    __shared__ float sm[1024];
    const int tid = threadIdx.x;
    float s = 0.f;
    for (int i = tid; i < B_ROWS; i += 1024) s += g_l1row[i];
    sm[tid] = s;
    __syncthreads();
    for (int off = 512; off > 0; off >>= 1) {
        if (tid < off) sm[tid] += sm[tid + off];
        __syncthreads();
    }
    if (tid == 0) out_l1[0] = sm[0] / (float)B_ROWS;
}

// ------------- streams/events (pre-main static init) ---------------
static cudaStream_t g_sG0, g_sG1, g_sS;       // two gemm lanes + select lane
static cudaEvent_t  g_evX[NCHUNKS];
static cudaEvent_t  g_evG[NCHUNKS];
static cudaEvent_t  g_evS;
static const bool g_res_init = [](){
    cudaStreamCreateWithFlags(&g_sG0, cudaStreamNonBlocking);
    cudaStreamCreateWithFlags(&g_sG1, cudaStreamNonBlocking);
    cudaStreamCreateWithFlags(&g_sS,  cudaStreamNonBlocking);
    for (int i = 0; i < NCHUNKS; i++) {
        cudaEventCreateWithFlags(&g_evX[i], cudaEventDisableTiming);
        cudaEventCreateWithFlags(&g_evG[i], cudaEventDisableTiming);
    }
    cudaEventCreateWithFlags(&g_evS, cudaEventDisableTiming);
    return true;
}();

// ---------------- launch: dual-GEMM-lane chunk pipeline ------------
extern "C" void kernel_launch(void* const* d_in, const int* in_sizes, int n_in,
                              void* d_out, int out_size)
{
    const float* x  = (const float*)d_in[0];
    const float* W1 = (const float*)d_in[1];
    const float* b1 = (const float*)d_in[2];
    const float* W2 = (const float*)d_in[3];
    const float* b2 = (const float*)d_in[4];

    float* out        = (float*)d_out;
    float* out_sparse = out;                                   // [B, D]
    float* out_mask   = out + (size_t)B_ROWS * D_DIM;          // [B, D]
    float* out_sp     = out + 2 * (size_t)B_ROWS * D_DIM;      // [B, 1]
    float* out_act    = out_sp + B_ROWS;                       // [B]
    float* out_l1     = out_act + B_ROWS;                      // [1]

    cudaFuncSetAttribute(gemm_predictor,
                         cudaFuncAttributeMaxDynamicSharedMemorySize, SM_DYN);

    cudaStream_t s0 = 0;
    const int conv_grid = (CHUNK_ROWS * D_DIM) / (4 * 256);    // 4096

    // lane 0 (origin): weight convert, then x chunks
    convert_w1<<<((size_t)D_DIM * H_DIM) / 256, 256, 0, s0>>>(W1);
    for (int c = 0; c < NCHUNKS; c++) {
        convert_x<<<conv_grid, 256, 0, s0>>>(x, c * CHUNK_ROWS);
        cudaEventRecord(g_evX[c], s0);
    }

    // gemm chunks alternate between two lanes so chunk tails overlap
    for (int c = 0; c < NCHUNKS; c++) {
        cudaStream_t sg = (c & 1) ? g_sG1 : g_sG0;
        cudaStreamWaitEvent(sg, g_evX[c], 0);
        gemm_predictor<<<dim3(8, CHUNK_ROWS / 128), 256, SM_DYN, sg>>>(
            b1, W2, c * (CHUNK_ROWS / 128));
        cudaEventRecord(g_evG[c], sg);
    }

    // select per chunk, gated on its gemm
    for (int c = 0; c < NCHUNKS; c++) {
        cudaStreamWaitEvent(g_sS, g_evG[c], 0);
        select_mask_kernel<<<CHUNK_ROWS, 256, 0, g_sS>>>(
            x, b2, out_sp, out_sparse, out_mask, out_act, c * CHUNK_ROWS);
    }
    cudaEventRecord(g_evS, g_sS);

    // rejoin origin, final reduction
    cudaStreamWaitEvent(s0, g_evS, 0);
    l1_reduce<<<1, 1024, 0, s0>>>(out_l1);
}